// round 11
// baseline (speedup 1.0000x reference)
#include <cuda_runtime.h>
#include <cstdint>

// Problem constants
#define BB 8
#define SS 4096
#define AA 3
#define KK 64
#define MARGIN 5.0f
#define ROWS (BB * SS)          // 32768
#define FLATN (SS * AA)         // 12288 per batch

// Output layout (float32):
//   [0] loss | [1..) predict_label (B,S,A) | total_idx (B*K,3) | candidate_label (B*K)
#define OFF_PRED 1
#define OFF_TI   (1 + ROWS * AA)            // 98305
#define OFF_CAND (OFF_TI + BB * KK * 3)     // 99841

#define NBLK 444    // 148 SMs x 3 blocks -> exactly one wave
#define MAXR 37     // teams 0..799 take 37 rows, 800..887 take 36
#define DEPTH 8     // bulk-copy pipeline depth (rows per team in flight)
#define STAGE_BYTES (2 * DEPTH * 4096)   // 64 KB dynamic smem per block

// Scratch (static device globals -- no allocations allowed)
__device__ float g_logits[ROWS * 6];     // full logits (768 KB)
__device__ int   g_selflat[BB * KK];     // selected flat indices
__device__ int   g_ctr;                  // completion counter (reset each run)

// ---- mbarrier helpers -------------------------------------------------------
__device__ __forceinline__ void mbar_init(uint32_t mbar, uint32_t count) {
    asm volatile("mbarrier.init.shared::cta.b64 [%0], %1;" :: "r"(mbar), "r"(count) : "memory");
}
__device__ __forceinline__ void mbar_expect_tx(uint32_t mbar, uint32_t bytes) {
    asm volatile("mbarrier.arrive.expect_tx.shared::cta.b64 _, [%0], %1;"
                 :: "r"(mbar), "r"(bytes) : "memory");
}
__device__ __forceinline__ void mbar_arrive(uint32_t mbar) {
    asm volatile("mbarrier.arrive.shared::cta.b64 _, [%0];" :: "r"(mbar) : "memory");
}
__device__ __forceinline__ void mbar_wait(uint32_t mbar, uint32_t phase) {
    asm volatile(
        "{\n\t"
        ".reg .pred P;\n\t"
        "LAB%=:\n\t"
        "mbarrier.try_wait.parity.acquire.cta.shared::cta.b64 P, [%0], %1;\n\t"
        "@!P bra LAB%=;\n\t"
        "}"
        :: "r"(mbar), "r"(phase) : "memory");
}
__device__ __forceinline__ void bulk_cp(uint32_t dst, const void* src,
                                        uint32_t bytes, uint32_t mbar) {
    asm volatile(
        "cp.async.bulk.shared::cta.global.mbarrier::complete_tx::bytes [%0], [%1], %2, [%3];"
        :: "r"(dst), "l"(src), "r"(bytes), "r"(mbar) : "memory");
}

// ---------------------------------------------------------------------------
// Single fused kernel, 128 threads (4 warps), occ 3.
//  Phase A (blocks 436..443): per-batch selection. Positives forced to exactly
//    2.0 (> any sigmoid < 1), stable top_k => first 64 ascending flat positions
//    with label==1. Labels are INT32 (jax x64 off).
//  Phase B (all blocks): X @ W + bias -> logits + predict_label.
//    2 warps per row-team; lane owns d = jq*256 + wu*128 + lane*4 + jj (96 W
//    regs). X rows stream through an 8-deep smem ring filled by ONE bulk copy
//    per row (producer = team's warp0/lane0), synced by full/empty mbarriers.
//    Race hardening vs R10: proxy fence after init, acquire waits, empty-
//    arrive AFTER compute. 18-SHFL butterfly; 2 warp partials combined in smem.
//  Phase C (last block): candidate_label + margin loss (fixed order).
// ---------------------------------------------------------------------------
__global__ void __launch_bounds__(128, 3)
k_fused(const float* __restrict__ X, const float* __restrict__ W,
        const float* __restrict__ bias, const int* __restrict__ labels,
        float* __restrict__ out)
{
    extern __shared__ float4 stage[];           // [2][DEPTH][256] float4
    __shared__ uint64_t mbFull[2 * DEPTH];      // [team][slot]
    __shared__ uint64_t mbEmpty[2 * DEPTH];
    __shared__ float sPart[2 * MAXR * 2 * 6];   // [team][row][warp-in-team][k]
    __shared__ float sFin[2 * MAXR * 6];        // [team][row][k]
    __shared__ int   s_idx[KK];
    __shared__ int   s_cnt[4];
    __shared__ float s_red[4];
    __shared__ int   s_flag;

    const int t    = threadIdx.x;        // 0..127
    const int warp = t >> 5;
    const int lane = t & 31;
    const int bid  = blockIdx.x;

    uint32_t fullB, emptyB, stageB;
    asm("{ .reg .u64 tt; cvta.to.shared.u64 tt, %1; cvt.u32.u64 %0, tt; }"
        : "=r"(fullB) : "l"(mbFull));
    asm("{ .reg .u64 tt; cvta.to.shared.u64 tt, %1; cvt.u32.u64 %0, tt; }"
        : "=r"(emptyB) : "l"(mbEmpty));
    asm("{ .reg .u64 tt; cvta.to.shared.u64 tt, %1; cvt.u32.u64 %0, tt; }"
        : "=r"(stageB) : "l"(stage));

    // Initialize mbarriers; proxy fence orders generic-proxy init before the
    // async proxy (bulk-copy engine) touches them.
    if (t == 0) {
#pragma unroll
        for (int i = 0; i < 2 * DEPTH; i++) {
            mbar_init(fullB  + 8u * i, 1);   // tx-based completion
            mbar_init(emptyB + 8u * i, 2);   // one arrive per consumer warp
        }
        asm volatile("fence.proxy.async.shared::cta;" ::: "memory");
    }
    __syncthreads();

    // ---------------- Phase A: selection (blocks 436..443) ----------------
    if (bid >= NBLK - BB) {
        const int b = bid - (NBLK - BB);
        const int* lab = labels + (size_t)b * FLATN;

        int found = 0;  // uniform across threads
        for (int base = 0; base < FLATN && found < KK; base += 128) {
            const int v = (lab[base + t] == 1);
            const unsigned m = __ballot_sync(0xffffffffu, v);
            if (lane == 0) s_cnt[warp] = __popc(m);
            __syncthreads();

            int wbase = found;
            for (int w = 0; w < warp; w++) wbase += s_cnt[w];
            const int g = wbase + __popc(m & ((1u << lane) - 1u));
            if (v && g < KK) s_idx[g] = base + t;

            int tot = 0;
#pragma unroll
            for (int w = 0; w < 4; w++) tot += s_cnt[w];
            found += tot;
            __syncthreads();
        }
        if (t < KK) {
            const int flat = s_idx[t];
            const int s = flat / AA;
            const int a = flat - s * AA;
            const size_t samp = (size_t)b * KK + t;
            g_selflat[samp] = flat;
            out[OFF_TI + samp * 3 + 0] = (float)b;
            out[OFF_TI + samp * 3 + 1] = (float)s;
            out[OFF_TI + samp * 3 + 2] = (float)a;
        }
        __syncthreads();   // smem reused below
    }

    // ---------------- Phase B: GEMM + logits + predict_label ----------------
    const int tw   = warp >> 1;              // team within block (0,1)
    const int wu   = warp & 1;               // warp within team
    const int team = bid * 2 + tw;           // 0..887
    const int start = team * 36 + min(team, 800);
    const int nr    = 36 + (team < 800 ? 1 : 0);

    // 96 W coefficients; lane owns d = jq*256 + wu*128 + lane*4 + jj
    float wR[96];
#pragma unroll
    for (int jq = 0; jq < 4; jq++)
#pragma unroll
        for (int jj = 0; jj < 4; jj++)
#pragma unroll
            for (int k = 0; k < 6; k++)
                wR[jq * 24 + jj * 6 + k] =
                    W[(jq * 256 + wu * 128 + lane * 4 + jj) * 6 + k];

    const int cf4 = wu * 32 + lane;                // f4 offset within row-quarter
    const bool producer = (wu == 0) && (lane == 0);
    const uint32_t teamStage = stageB + (uint32_t)tw * (DEPTH * 4096);
    const uint32_t teamFull  = fullB  + (uint32_t)tw * (DEPTH * 8);
    const uint32_t teamEmpty = emptyB + (uint32_t)tw * (DEPTH * 8);

    // Preload DEPTH rows: one bulk copy each (nr >= 36 > DEPTH).
    if (producer) {
#pragma unroll
        for (int i = 0; i < DEPTH; i++) {
            mbar_expect_tx(teamFull + 8u * i, 4096);
            bulk_cp(teamStage + (uint32_t)i * 4096,
                    X + (size_t)(start + i) * 1024, 4096, teamFull + 8u * i);
        }
    }

    for (int r = 0; r < nr; r++) {
        const int slot = r & (DEPTH - 1);
        const uint32_t ph = (uint32_t)((r / DEPTH) & 1);

        // 1. wait row resident (acquire)
        mbar_wait(teamFull + 8u * slot, ph);

        // 2. load registers from smem (linear layout == R9's verified layout)
        const float4* sl = stage + (tw * DEPTH + slot) * 256 + cf4;
        const float4 c0 = sl[0];
        const float4 c1 = sl[64];
        const float4 c2 = sl[128];
        const float4 c3 = sl[192];

        // 3. compute (smem fully consumed into registers before any release)
        const float xv[16] = {c0.x, c0.y, c0.z, c0.w,  c1.x, c1.y, c1.z, c1.w,
                              c2.x, c2.y, c2.z, c2.w,  c3.x, c3.y, c3.z, c3.w};
        float acc[6];
#pragma unroll
        for (int k = 0; k < 6; k++) acc[k] = 0.0f;
#pragma unroll
        for (int j = 0; j < 16; j++)
#pragma unroll
            for (int k = 0; k < 6; k++)
                acc[k] = fmaf(xv[j], wR[j * 6 + k], acc[k]);

        // 18-SHFL folded butterfly: stage 16 folds 6 accs -> 3 per half-warp.
        float o[6];
#pragma unroll
        for (int k = 0; k < 6; k++) o[k] = __shfl_xor_sync(0xffffffffu, acc[k], 16);
        float q0, q1, q2;
        if (lane < 16) { q0 = acc[0] + o[0]; q1 = acc[1] + o[1]; q2 = acc[2] + o[2]; }
        else           { q0 = acc[3] + o[3]; q1 = acc[4] + o[4]; q2 = acc[5] + o[5]; }
#pragma unroll
        for (int off = 8; off > 0; off >>= 1) {
            q0 += __shfl_xor_sync(0xffffffffu, q0, off);
            q1 += __shfl_xor_sync(0xffffffffu, q1, off);
            q2 += __shfl_xor_sync(0xffffffffu, q2, off);
        }
        float* dst = &sPart[((tw * MAXR + r) * 2 + wu) * 6];
        if (lane == 0)  { dst[0] = q0; dst[1] = q1; dst[2] = q2; }
        if (lane == 16) { dst[3] = q0; dst[4] = q1; dst[5] = q2; }

        // 4. release slot (after compute: LDS long retired)
        if (lane == 0) mbar_arrive(teamEmpty + 8u * slot);

        // 5. producer refills slot with row r+DEPTH once both warps released
        if (producer) {
            const int rf = r + DEPTH;
            if (rf < nr) {
                mbar_wait(teamEmpty + 8u * slot, ph);
                mbar_expect_tx(teamFull + 8u * slot, 4096);
                bulk_cp(teamStage + (uint32_t)slot * 4096,
                        X + (size_t)(start + rf) * 1024, 4096,
                        teamFull + 8u * slot);
            }
        }
    }
    __syncthreads();

    // Cross-warp (2 partials) combine + bias; write logits, keep in smem.
    for (int v = t; v < 2 * nr * 6; v += 128) {
        const int tw2 = v / (nr * 6);
        const int rem = v - tw2 * nr * 6;
        const int row = rem / 6;
        const int k   = rem - row * 6;
        const int team2 = bid * 2 + tw2;
        const int st2   = team2 * 36 + min(team2, 800);
        float s = __ldg(&bias[k])
                + sPart[((tw2 * MAXR + row) * 2 + 0) * 6 + k]
                + sPart[((tw2 * MAXR + row) * 2 + 1) * 6 + k];
        g_logits[(size_t)(st2 + row) * 6 + k] = s;
        sFin[(tw2 * MAXR + row) * 6 + k] = s;
    }
    __syncthreads();

    // predict_label: argmax over C=2, first-max tie-break => 1 iff p1 > p0.
    for (int u = t; u < 2 * nr * 3; u += 128) {
        const int tw2 = u / (nr * 3);
        const int rem = u - tw2 * nr * 3;
        const int row = rem / 3;
        const int a   = rem - row * 3;
        const int team2 = bid * 2 + tw2;
        const int st2   = team2 * 36 + min(team2, 800);
        out[OFF_PRED + (size_t)(st2 + row) * 3 + a] =
            (sFin[(tw2 * MAXR + row) * 6 + 2 * a + 1] >
             sFin[(tw2 * MAXR + row) * 6 + 2 * a]) ? 1.0f : 0.0f;
    }

    // ---------------- Phase C: last block computes loss + candidate ----------
    __threadfence();
    if (t == 0) s_flag = (atomicAdd(&g_ctr, 1) == NBLK - 1) ? 1 : 0;
    __syncthreads();
    if (!s_flag) return;
    __threadfence();   // acquire: all blocks' logits/selflat visible

    float term = 0.0f;
#pragma unroll
    for (int i = 0; i < 4; i++) {
        const int samp = t + i * 128;                 // 512 samples total
        const int flat = g_selflat[samp];
        const int b2 = samp >> 6;                     // samp / KK
        const int s2 = flat / AA;
        const int a2 = flat - s2 * AA;
        const int row = b2 * SS + s2;
        const float p0 = g_logits[(size_t)row * 6 + 2 * a2];
        const float p1 = g_logits[(size_t)row * 6 + 2 * a2 + 1];
        out[OFF_CAND + samp] = (p1 > p0) ? 1.0f : 0.0f;
        // selected positions always have label 1 => y = 1; C = 2
        term += fmaxf(0.0f, MARGIN - p1 + p0) * 0.5f;
    }
#pragma unroll
    for (int off = 16; off > 0; off >>= 1)
        term += __shfl_xor_sync(0xffffffffu, term, off);
    if (lane == 0) s_red[warp] = term;
    __syncthreads();
    if (t == 0) {
        float tot = 0.0f;
#pragma unroll
        for (int w = 0; w < 4; w++) tot += s_red[w];
        out[0] = tot / (float)(BB * KK);
        g_ctr = 0;   // ready for next graph replay
    }
}

// ---------------------------------------------------------------------------
extern "C" void kernel_launch(void* const* d_in, const int* in_sizes, int n_in,
                              void* d_out, int out_size)
{
    const float* X      = (const float*)d_in[0];    // (B,S,D) f32
    const float* W      = (const float*)d_in[1];    // (D, A*C) f32
    const float* bias   = (const float*)d_in[2];    // (A*C,) f32
    const int*   labels = (const int*)d_in[3];      // (B,S,A) int32 (jax x64 off)
    float*       out    = (float*)d_out;

    // Not an allocation; deterministic; capture-safe.
    cudaFuncSetAttribute(k_fused, cudaFuncAttributeMaxDynamicSharedMemorySize,
                         STAGE_BYTES);
    k_fused<<<NBLK, 128, STAGE_BYTES>>>(X, W, bias, labels, out);
}

// round 13
// speedup vs baseline: 2.8174x; 2.8174x over previous
#include <cuda_runtime.h>
#include <cstdint>

// Problem constants
#define BB 8
#define SS 4096
#define AA 3
#define KK 64
#define MARGIN 5.0f
#define ROWS (BB * SS)          // 32768
#define FLATN (SS * AA)         // 12288 per batch

// Output layout (float32):
//   [0] loss | [1..) predict_label (B,S,A) | total_idx (B*K,3) | candidate_label (B*K)
#define OFF_PRED 1
#define OFF_TI   (1 + ROWS * AA)            // 98305
#define OFF_CAND (OFF_TI + BB * KK * 3)     // 99841

#define NBLK 888    // 148 SMs x 6 blocks -> exactly one wave
#define MAXR 37     // blocks 0..799 take 37 rows, 800..887 take 36
#define DEPTH 8     // cp.async ring depth (rows in flight per block)
#define STAGE_BYTES (DEPTH * 4096)       // 32 KB dynamic smem per block

// (Resubmission of round-12 kernel: previous bench was an infra failure,
//  "GB300 container failed twice" — no kernel signal received.)

// Scratch (static device globals -- no allocations allowed)
__device__ float g_logits[ROWS * 6];     // full logits (768 KB)
__device__ int   g_selflat[BB * KK];     // selected flat indices
__device__ int   g_ctr;                  // completion counter (reset each run)

__device__ __forceinline__ void cp16(uint32_t dst_smem, const void* src) {
    asm volatile("cp.async.cg.shared.global [%0], [%1], 16;"
                 :: "r"(dst_smem), "l"(src));
}
#define CP_COMMIT()  asm volatile("cp.async.commit_group;" ::: "memory")
#define CP_WAIT7()   asm volatile("cp.async.wait_group 7;" ::: "memory")

// ---------------------------------------------------------------------------
// Single fused kernel, 128 threads (4 warps), occ 6 (24 warps/SM).
//  Phase A (blocks 880..887): per-batch selection. Positives forced to exactly
//    2.0 (> any sigmoid < 1), stable top_k => first 64 ascending flat positions
//    with label==1. Labels are INT32 (jax x64 off).
//  Phase B (all blocks): X @ W + bias -> logits + predict_label.
//    4 warps per row; thread t owns d in {4t..4t+3} U {512+4t..512+4t+3}
//    (48 W regs -> ~75 regs total -> occupancy 6). X rows stream through an
//    8-deep cp.async smem ring; each thread copies exactly the 2x16B chunks it
//    later reads -> its own wait_group is the only sync (R9-verified pattern).
//    18-SHFL folded butterfly per warp; 4 warp partials combined in smem.
//  Phase C (last block): candidate_label + margin loss (fixed order).
// ---------------------------------------------------------------------------
__global__ void __launch_bounds__(128, 6)
k_fused(const float* __restrict__ X, const float* __restrict__ W,
        const float* __restrict__ bias, const int* __restrict__ labels,
        float* __restrict__ out)
{
    extern __shared__ float4 stage[];           // [DEPTH][256] float4 (32 KB)
    __shared__ float sPart[MAXR * 4 * 6];       // [row][warp][k]
    __shared__ float sFin[MAXR * 6];            // [row][k]
    __shared__ int   s_idx[KK];
    __shared__ int   s_cnt[4];
    __shared__ float s_red[4];
    __shared__ int   s_flag;

    const int t    = threadIdx.x;        // 0..127
    const int warp = t >> 5;
    const int lane = t & 31;
    const int bid  = blockIdx.x;

    // ---------------- Phase A: selection (blocks 880..887) ----------------
    if (bid >= NBLK - BB) {
        const int b = bid - (NBLK - BB);
        const int* lab = labels + (size_t)b * FLATN;

        int found = 0;  // uniform across threads
        for (int base = 0; base < FLATN && found < KK; base += 128) {
            const int v = (lab[base + t] == 1);
            const unsigned m = __ballot_sync(0xffffffffu, v);
            if (lane == 0) s_cnt[warp] = __popc(m);
            __syncthreads();

            int wbase = found;
            for (int w = 0; w < warp; w++) wbase += s_cnt[w];
            const int g = wbase + __popc(m & ((1u << lane) - 1u));
            if (v && g < KK) s_idx[g] = base + t;

            int tot = 0;
#pragma unroll
            for (int w = 0; w < 4; w++) tot += s_cnt[w];
            found += tot;
            __syncthreads();
        }
        if (t < KK) {
            const int flat = s_idx[t];
            const int s = flat / AA;
            const int a = flat - s * AA;
            const size_t samp = (size_t)b * KK + t;
            g_selflat[samp] = flat;
            out[OFF_TI + samp * 3 + 0] = (float)b;
            out[OFF_TI + samp * 3 + 1] = (float)s;
            out[OFF_TI + samp * 3 + 2] = (float)a;
        }
        __syncthreads();   // smem reused below
    }

    // ---------------- Phase B: GEMM + logits + predict_label ----------------
    const int start = bid * 36 + min(bid, 800);
    const int nr    = 36 + (bid < 800 ? 1 : 0);

    // wA[j*6+k] = W[4t + j][k],  wB[j*6+k] = W[512 + 4t + j][k]
    float wA[24], wB[24];
#pragma unroll
    for (int i = 0; i < 24; i++) {
        wA[i] = W[t * 24 + i];
        wB[i] = W[(512 + 4 * t) * 6 + i];
    }

    const float4* __restrict__ X4 = reinterpret_cast<const float4*>(X);

    uint32_t stageB;
    asm("{ .reg .u64 tt; cvta.to.shared.u64 tt, %1; cvt.u32.u64 %0, tt; }"
        : "=r"(stageB) : "l"(stage));
    const uint32_t myA = stageB + (uint32_t)t * 16;           // slot 0, xa chunk
    const uint32_t myBq = myA + 2048;                          // xb chunk

    // Preload DEPTH rows (one commit-group per row; nr >= 36 > DEPTH).
#pragma unroll
    for (int i = 0; i < DEPTH; i++) {
        const float4* srow = X4 + (size_t)(start + i) * 256 + t;
        cp16(myA  + (uint32_t)i * 4096, srow);
        cp16(myBq + (uint32_t)i * 4096, srow + 128);
        CP_COMMIT();
    }

    for (int r = 0; r < nr; r++) {
        CP_WAIT7();                              // oldest group (row r) resident
        const int slot = r & (DEPTH - 1);
        const float4* sl = stage + slot * 256;
        const float4 ca = sl[t];
        const float4 cb = sl[128 + t];

        // Refill this slot with row r+DEPTH; uniform commit count per iter.
        const int rf = r + DEPTH;
        if (rf < nr) {
            const float4* srow = X4 + (size_t)(start + rf) * 256 + t;
            cp16(myA  + (uint32_t)slot * 4096, srow);
            cp16(myBq + (uint32_t)slot * 4096, srow + 128);
        }
        CP_COMMIT();

        const float xav[4] = {ca.x, ca.y, ca.z, ca.w};
        const float xbv[4] = {cb.x, cb.y, cb.z, cb.w};
        float acc[6];
#pragma unroll
        for (int k = 0; k < 6; k++) acc[k] = 0.0f;
#pragma unroll
        for (int j = 0; j < 4; j++)
#pragma unroll
            for (int k = 0; k < 6; k++) {
                acc[k] = fmaf(xav[j], wA[j * 6 + k], acc[k]);
                acc[k] = fmaf(xbv[j], wB[j * 6 + k], acc[k]);
            }

        // 18-SHFL folded butterfly: stage 16 folds 6 accs -> 3 per half-warp.
        float o[6];
#pragma unroll
        for (int k = 0; k < 6; k++) o[k] = __shfl_xor_sync(0xffffffffu, acc[k], 16);
        float q0, q1, q2;
        if (lane < 16) { q0 = acc[0] + o[0]; q1 = acc[1] + o[1]; q2 = acc[2] + o[2]; }
        else           { q0 = acc[3] + o[3]; q1 = acc[4] + o[4]; q2 = acc[5] + o[5]; }
#pragma unroll
        for (int off = 8; off > 0; off >>= 1) {
            q0 += __shfl_xor_sync(0xffffffffu, q0, off);
            q1 += __shfl_xor_sync(0xffffffffu, q1, off);
            q2 += __shfl_xor_sync(0xffffffffu, q2, off);
        }
        // lane 0: this warp's totals for k=0..2; lane 16: k=3..5.
        float* dst = &sPart[(r * 4 + warp) * 6];
        if (lane == 0)  { dst[0] = q0; dst[1] = q1; dst[2] = q2; }
        if (lane == 16) { dst[3] = q0; dst[4] = q1; dst[5] = q2; }
    }
    __syncthreads();

    // Cross-warp (4 partials) combine + bias; write logits, keep in smem.
    for (int v = t; v < nr * 6; v += 128) {
        const int row = v / 6;
        const int k   = v - row * 6;
        float s = __ldg(&bias[k]);
#pragma unroll
        for (int w = 0; w < 4; w++) s += sPart[(row * 4 + w) * 6 + k];
        g_logits[(size_t)(start + row) * 6 + k] = s;
        sFin[v] = s;
    }
    __syncthreads();

    // predict_label: argmax over C=2, first-max tie-break => 1 iff p1 > p0.
    for (int u = t; u < nr * 3; u += 128) {
        const int row = u / 3;
        const int a   = u - row * 3;
        out[OFF_PRED + (size_t)(start + row) * 3 + a] =
            (sFin[row * 6 + 2 * a + 1] > sFin[row * 6 + 2 * a]) ? 1.0f : 0.0f;
    }

    // ---------------- Phase C: last block computes loss + candidate ----------
    __threadfence();
    if (t == 0) s_flag = (atomicAdd(&g_ctr, 1) == NBLK - 1) ? 1 : 0;
    __syncthreads();
    if (!s_flag) return;
    __threadfence();   // acquire: all blocks' logits/selflat visible

    float term = 0.0f;
#pragma unroll
    for (int i = 0; i < 4; i++) {
        const int samp = t + i * 128;                 // 512 samples total
        const int flat = g_selflat[samp];
        const int b2 = samp >> 6;                     // samp / KK
        const int s2 = flat / AA;
        const int a2 = flat - s2 * AA;
        const int row = b2 * SS + s2;
        const float p0 = g_logits[(size_t)row * 6 + 2 * a2];
        const float p1 = g_logits[(size_t)row * 6 + 2 * a2 + 1];
        out[OFF_CAND + samp] = (p1 > p0) ? 1.0f : 0.0f;
        // selected positions always have label 1 => y = 1; C = 2
        term += fmaxf(0.0f, MARGIN - p1 + p0) * 0.5f;
    }
#pragma unroll
    for (int off = 16; off > 0; off >>= 1)
        term += __shfl_xor_sync(0xffffffffu, term, off);
    if (lane == 0) s_red[warp] = term;
    __syncthreads();
    if (t == 0) {
        float tot = 0.0f;
#pragma unroll
        for (int w = 0; w < 4; w++) tot += s_red[w];
        out[0] = tot / (float)(BB * KK);
        g_ctr = 0;   // ready for next graph replay
    }
}

// ---------------------------------------------------------------------------
extern "C" void kernel_launch(void* const* d_in, const int* in_sizes, int n_in,
                              void* d_out, int out_size)
{
    const float* X      = (const float*)d_in[0];    // (B,S,D) f32
    const float* W      = (const float*)d_in[1];    // (D, A*C) f32
    const float* bias   = (const float*)d_in[2];    // (A*C,) f32
    const int*   labels = (const int*)d_in[3];      // (B,S,A) int32 (jax x64 off)
    float*       out    = (float*)d_out;

    // Not an allocation; deterministic; capture-safe.
    cudaFuncSetAttribute(k_fused, cudaFuncAttributeMaxDynamicSharedMemorySize,
                         STAGE_BYTES);
    k_fused<<<NBLK, 128, STAGE_BYTES>>>(X, W, bias, labels, out);
}